// round 5
// baseline (speedup 1.0000x reference)
#include <cuda_runtime.h>
#include <stdint.h>

#define TT 256
#define BB 64
#define HH 512
#define RC_CTAS 128

typedef unsigned long long ull;

// -------- scratch (__device__ globals) --------
static __device__ float g_gx[(size_t)8 * TT * HH * BB];      // [dg][t][h][b]
static __device__ float g_out0[(size_t)TT * BB * 2 * HH];    // [t][b][2H]
static __device__ float g_A[8 * HH * BB];                    // [dg][h][b]  (= h*noise)
static __device__ float g_noiseT[8 * HH * BB];               // [dg][h][b]
static __device__ unsigned g_bar_count;
static __device__ unsigned g_bar_gen;

// -------------------- helpers --------------------
__device__ __forceinline__ void ffma2(ull& d, ull a, ull b) {
    asm("fma.rn.f32x2 %0, %1, %2, %0;" : "+l"(d) : "l"(a), "l"(b));
}
__device__ __forceinline__ float2 unpack2(ull v) {
    float2 r;
    asm("mov.b64 {%0, %1}, %2;" : "=f"(r.x), "=f"(r.y) : "l"(v));
    return r;
}
__device__ __forceinline__ void cp_async16(uint32_t s, const void* g) {
    asm volatile("cp.async.ca.shared.global [%0], [%1], 16;" :: "r"(s), "l"(g));
}
__device__ __forceinline__ float fsig(float x) {
    return __fdividef(1.f, 1.f + __expf(-x));
}
__device__ __forceinline__ float ftanh(float x) {
    return 2.f * fsig(2.f * x) - 1.f;
}

// -------------------- barrier reset (separate launch, stream-ordered) ----
__global__ void zero_bar_kernel() {
    g_bar_count = 0;
    g_bar_gen = 0;
}

// -------------------- noise transpose: [dg][b][h] -> [dg][h][b] ---------
__global__ void noiseT_kernel(const float* __restrict__ nh) {
    __shared__ float tile[32][33];
    int dg = blockIdx.z;
    int h0 = blockIdx.x * 32, b0 = blockIdx.y * 32;
    int x = threadIdx.x, y = threadIdx.y;   // 32 x 8
    #pragma unroll
    for (int i = 0; i < 32; i += 8)
        tile[y + i][x] = nh[(size_t)dg * BB * HH + (size_t)(b0 + y + i) * HH + h0 + x];
    __syncthreads();
    #pragma unroll
    for (int i = 0; i < 32; i += 8)
        g_noiseT[(size_t)dg * HH * BB + (size_t)(h0 + y + i) * BB + b0 + x] = tile[x][y + i];
}

// -------------------- gx GEMM (writes [dg][t][h][b]) --------------------
template<int K>
__global__ __launch_bounds__(128)
void gx_gemm_kernel(const float* __restrict__ X,
                    const float* __restrict__ Noise,
                    const float* __restrict__ W,
                    const float* __restrict__ bih,
                    const float* __restrict__ bhh)
{
    const int dg = blockIdx.z;
    const int mt = blockIdx.y;
    const int nt = blockIdx.x;
    const int tid = threadIdx.x;

    __shared__ float As[16][68];
    __shared__ float Bs[16][136];

    const float* Xbase = (K == 1024) ? (const float*)g_out0 : X;
    const float* Xp = Xbase + (size_t)mt * BB * K;
    const float* Np = Noise + (size_t)dg * BB * K;
    const float* Wp = W + (size_t)dg * K * HH + nt * 64;

    ull accp[4][4];
    #pragma unroll
    for (int p = 0; p < 4; p++)
        #pragma unroll
        for (int j = 0; j < 4; j++) accp[p][j] = 0ULL;

    const int a_lm = tid >> 2;
    const int a_lk = (tid & 3) * 4;
    const int b_lk = tid >> 4;
    const int b_ln = (tid & 15) * 4;
    const int tm = (tid >> 4) * 8;
    const int tn = (tid & 15) * 4;

    for (int k0 = 0; k0 < K; k0 += 16) {
        #pragma unroll
        for (int p = 0; p < 2; p++) {
            int lm = a_lm + p * 32;
            float4 xv = *reinterpret_cast<const float4*>(Xp + (size_t)lm * K + k0 + a_lk);
            float4 nv = *reinterpret_cast<const float4*>(Np + (size_t)lm * K + k0 + a_lk);
            As[a_lk + 0][lm] = xv.x * nv.x;
            As[a_lk + 1][lm] = xv.y * nv.y;
            As[a_lk + 2][lm] = xv.z * nv.z;
            As[a_lk + 3][lm] = xv.w * nv.w;
        }
        #pragma unroll
        for (int p = 0; p < 2; p++) {
            int lk = b_lk + p * 8;
            float4 w = *reinterpret_cast<const float4*>(Wp + (size_t)(k0 + lk) * HH + b_ln);
            *reinterpret_cast<float4*>(&Bs[lk][b_ln * 2])     = make_float4(w.x, w.x, w.y, w.y);
            *reinterpret_cast<float4*>(&Bs[lk][b_ln * 2 + 4]) = make_float4(w.z, w.z, w.w, w.w);
        }
        __syncthreads();

        #pragma unroll
        for (int kk = 0; kk < 16; kk++) {
            ulonglong2 av0 = *reinterpret_cast<const ulonglong2*>(&As[kk][tm]);
            ulonglong2 av1 = *reinterpret_cast<const ulonglong2*>(&As[kk][tm + 4]);
            ulonglong2 bv0 = *reinterpret_cast<const ulonglong2*>(&Bs[kk][tn * 2]);
            ulonglong2 bv1 = *reinterpret_cast<const ulonglong2*>(&Bs[kk][tn * 2 + 4]);
            ull a[4] = {av0.x, av0.y, av1.x, av1.y};
            ull b[4] = {bv0.x, bv0.y, bv1.x, bv1.y};
            #pragma unroll
            for (int p = 0; p < 4; p++)
                #pragma unroll
                for (int j = 0; j < 4; j++)
                    ffma2(accp[p][j], a[p], b[j]);
        }
        __syncthreads();
    }

    // write transposed: g_gx[dg][t][h][b]
    float* Cp = g_gx + ((size_t)dg * TT + mt) * HH * BB;
    #pragma unroll
    for (int j = 0; j < 4; j++) {
        float bias = bih[dg * HH + nt * 64 + tn + j] + bhh[dg * HH + nt * 64 + tn + j];
        float2 u0 = unpack2(accp[0][j]);
        float2 u1 = unpack2(accp[1][j]);
        float2 u2 = unpack2(accp[2][j]);
        float2 u3 = unpack2(accp[3][j]);
        float4 lo = make_float4(u0.x + bias, u0.y + bias, u1.x + bias, u1.y + bias);
        float4 hi = make_float4(u2.x + bias, u2.y + bias, u3.x + bias, u3.y + bias);
        float* dst = Cp + (size_t)(nt * 64 + tn + j) * BB + tm;
        *reinterpret_cast<float4*>(dst)     = lo;
        *reinterpret_cast<float4*>(dst + 4) = hi;
    }
}

// -------------------- persistent recurrence v2 --------------------
// 128 CTAs: d = cta>>6, slice = cta&63 -> cols [slice*8, slice*8+8) of ALL 4 gates.
// 256 threads: gate g = tid>>6 (2 warps per gate).
// Ws (dynamic, 128KB): w_hh dup pairs [g][k][16].
// h/c state lives in registers. One grid barrier per step.
__global__ __launch_bounds__(256, 1)
void recur_kernel(const float* __restrict__ Whh,
                  const float* __restrict__ mask,
                  float* __restrict__ outp,
                  int layer,
                  float* __restrict__ hn,
                  float* __restrict__ cn)
{
    extern __shared__ float Ws[];                      // [4][512][16] = 128KB
    __shared__ __align__(16) float Asb[2][4][16][64];  // 32KB
    __shared__ __align__(16) float Gs[4][8][64];       // 8KB

    const int cta = blockIdx.x;
    const int d    = cta >> 6;
    const int col0 = (cta & 63) * 8;
    const int tid  = threadIdx.x;

    const int g      = tid >> 6;
    const int tid_g  = tid & 63;
    const int half   = tid_g >> 5;
    const int lane   = tid & 31;
    const int cp     = lane >> 3;            // 0..3 col pair
    const int bq     = half * 8 + (lane & 7); // 0..15, batches 4bq..4bq+3

    float* op = (layer == 0) ? (float*)g_out0 : outp;

    // ---- load W slice, duplicated pairs: Ws[g][k][cp*4..] = (w2cp,w2cp,w2cp+1,w2cp+1)
    {
        const float* Wb = Whh + (size_t)d * 4 * HH * HH + col0;
        for (int it = 0; it < 16; ++it) {
            int i = tid + it * 256;                 // 0..4095
            int gg = i >> 10;
            int k  = (i >> 1) & 511;
            int h4 = (i & 1) * 4;
            float4 w = *reinterpret_cast<const float4*>(
                Wb + ((size_t)gg * HH + k) * HH + h4);
            float* dst = Ws + ((gg * 512 + k) << 4) + h4 * 2;
            *reinterpret_cast<float4*>(dst)     = make_float4(w.x, w.x, w.y, w.y);
            *reinterpret_cast<float4*>(dst + 4) = make_float4(w.z, w.z, w.w, w.w);
        }
    }
    // ---- zero A (h0 = 0 -> recurrent term 0)
    #pragma unroll
    for (int i = 0; i < 8; i++)
        g_A[cta * 2048 + tid + i * 256] = 0.f;

    // ---- barrier machinery (monotonic within launch; reset by zero_bar)
    unsigned bar_n = 0;
    const bool is_leader = (cta == 0);
    auto grid_bar = [&]() {
        __syncthreads();
        bar_n++;
        if (tid == 0) {
            asm volatile("red.release.gpu.global.add.u32 [%0], %1;"
                         :: "l"(&g_bar_count), "r"(1u) : "memory");
            if (is_leader) {
                unsigned c;
                do {
                    asm volatile("ld.acquire.gpu.global.u32 %0, [%1];"
                                 : "=r"(c) : "l"(&g_bar_count) : "memory");
                } while (c < bar_n * RC_CTAS);
                asm volatile("st.release.gpu.global.u32 [%0], %1;"
                             :: "l"(&g_bar_gen), "r"(bar_n) : "memory");
            } else {
                unsigned gv;
                do {
                    asm volatile("ld.acquire.gpu.global.u32 %0, [%1];"
                                 : "=r"(gv) : "l"(&g_bar_gen) : "memory");
                } while (gv < bar_n);
            }
        }
        __syncthreads();
    };

    grid_bar();

    // pointwise mapping (stable across steps -> h/c in registers)
    const int pc = tid >> 5;          // 0..7  column within slice
    const int pb = (tid & 31) * 2;    // batch pair
    float2 c_reg = make_float2(0.f, 0.f);
    float2 h_reg = make_float2(0.f, 0.f);

    const float* Abase = g_A + (size_t)d * 4 * HH * BB;
    const uint32_t as_u32 = (uint32_t)__cvta_generic_to_shared(&Asb[0][0][0][0]);
    const float* wsp = Ws + (g * 512) * 16 + cp * 4;
    const float* asg = &Asb[0][g][0][0];

    for (int step = 0; step < TT; ++step) {
        const int t = (d == 0) ? step : (TT - 1 - step);

        // prefetch gx for this thread's GEMM cells (gx[dg][t][h][b])
        const float* gxp = g_gx + (((size_t)(d * 4 + g) * TT + t) * HH + col0) * BB;
        float4 gx0 = *reinterpret_cast<const float4*>(gxp + (size_t)(2 * cp) * BB + 4 * bq);
        float4 gx1 = *reinterpret_cast<const float4*>(gxp + (size_t)(2 * cp + 1) * BB + 4 * bq);

        // ---- GEMM: all 4 gates, this CTA's 8 cols; A double-buffered via cp.async
        {
            // stage chunk 0: 1024 x 16B, 4 per thread
            #pragma unroll
            for (int i = 0; i < 4; i++) {
                int u = tid + i * 256;
                int ug = u >> 8, uk = (u >> 4) & 15, ub = u & 15;
                cp_async16(as_u32 + u * 16,
                           Abase + ((size_t)ug * HH + uk) * BB + ub * 4);
            }
            asm volatile("cp.async.commit_group;");
        }

        ull a00 = 0, a01 = 0, a10 = 0, a11 = 0;
        #pragma unroll 1
        for (int ch = 0; ch < 32; ++ch) {
            asm volatile("cp.async.wait_group 0;");
            __syncthreads();
            if (ch < 31) {
                int k0n = (ch + 1) * 16;
                uint32_t dbuf = as_u32 + (((ch + 1) & 1) << 14);
                #pragma unroll
                for (int i = 0; i < 4; i++) {
                    int u = tid + i * 256;
                    int ug = u >> 8, uk = (u >> 4) & 15, ub = u & 15;
                    cp_async16(dbuf + u * 16,
                               Abase + ((size_t)ug * HH + k0n + uk) * BB + ub * 4);
                }
            }
            asm volatile("cp.async.commit_group;");

            const float* asr = asg + ((ch & 1) ? 4096 : 0);
            const float* wr  = wsp + (ch << 8);   // ch*16*16
            #pragma unroll
            for (int kk = 0; kk < 16; kk++) {
                ulonglong2 a2 = *reinterpret_cast<const ulonglong2*>(asr + kk * 64 + bq * 4);
                ulonglong2 w2 = *reinterpret_cast<const ulonglong2*>(wr + (kk << 4));
                ffma2(a00, a2.x, w2.x);
                ffma2(a01, a2.y, w2.x);
                ffma2(a10, a2.x, w2.y);
                ffma2(a11, a2.y, w2.y);
            }
        }

        // ---- epilogue: gates -> SMEM (local exchange)
        {
            float2 u00 = unpack2(a00), u01 = unpack2(a01);
            float2 u10 = unpack2(a10), u11 = unpack2(a11);
            *reinterpret_cast<float4*>(&Gs[g][2 * cp][4 * bq]) =
                make_float4(u00.x + gx0.x, u00.y + gx0.y, u01.x + gx0.z, u01.y + gx0.w);
            *reinterpret_cast<float4*>(&Gs[g][2 * cp + 1][4 * bq]) =
                make_float4(u10.x + gx1.x, u10.y + gx1.y, u11.x + gx1.z, u11.y + gx1.w);
        }
        __syncthreads();

        // ---- pointwise LSTM cell (CTA-local, state in registers)
        {
            float2 gi = *reinterpret_cast<const float2*>(&Gs[0][pc][pb]);
            float2 gf = *reinterpret_cast<const float2*>(&Gs[1][pc][pb]);
            float2 gg = *reinterpret_cast<const float2*>(&Gs[2][pc][pb]);
            float2 go = *reinterpret_cast<const float2*>(&Gs[3][pc][pb]);
            float2 mt = *reinterpret_cast<const float2*>(mask + t * BB + pb);

            float2 hm, cm;
            {
                float cnew = fsig(gf.x) * c_reg.x + fsig(gi.x) * ftanh(gg.x);
                float hnew = fsig(go.x) * ftanh(cnew);
                hm.x = hnew * mt.x + h_reg.x * (1.f - mt.x);
                cm.x = cnew * mt.x + c_reg.x * (1.f - mt.x);
            }
            {
                float cnew = fsig(gf.y) * c_reg.y + fsig(gi.y) * ftanh(gg.y);
                float hnew = fsig(go.y) * ftanh(cnew);
                hm.y = hnew * mt.y + h_reg.y * (1.f - mt.y);
                cm.y = cnew * mt.y + c_reg.y * (1.f - mt.y);
            }
            h_reg = hm; c_reg = cm;

            // A = h * noise for all 4 gates (coalesced 256B per warp)
            const int hcol = col0 + pc;
            #pragma unroll
            for (int gg2 = 0; gg2 < 4; gg2++) {
                int ai = (((d * 4 + gg2) * HH) + hcol) * BB + pb;
                float2 nz = *reinterpret_cast<const float2*>(&g_noiseT[ai]);
                *reinterpret_cast<float2*>(&g_A[ai]) = make_float2(hm.x * nz.x, hm.y * nz.y);
            }

            // sequence output [t][b][2H]
            size_t ob = (size_t)t * BB * 2 * HH + (size_t)pb * 2 * HH + d * HH + hcol;
            op[ob] = hm.x;
            op[ob + 2 * HH] = hm.y;

            if (step == TT - 1) {
                size_t oi = ((size_t)(layer * 2 + d) * BB + pb) * HH + hcol;
                hn[oi] = hm.x; hn[oi + HH] = hm.y;
                cn[oi] = cm.x; cn[oi + HH] = cm.y;
            }
        }

        grid_bar();
    }
}

// -------------------- launch --------------------
extern "C" void kernel_launch(void* const* d_in, const int* in_sizes, int n_in,
                              void* d_out, int out_size)
{
    const float* x      = (const float*)d_in[0];
    const float* mask   = (const float*)d_in[1];
    const float* w_ih0  = (const float*)d_in[2];
    const float* w_hh0  = (const float*)d_in[3];
    const float* b_ih0  = (const float*)d_in[4];
    const float* b_hh0  = (const float*)d_in[5];
    const float* n_in0  = (const float*)d_in[6];
    const float* n_hid0 = (const float*)d_in[7];
    const float* w_ih1  = (const float*)d_in[8];
    const float* w_hh1  = (const float*)d_in[9];
    const float* b_ih1  = (const float*)d_in[10];
    const float* b_hh1  = (const float*)d_in[11];
    const float* n_in1  = (const float*)d_in[12];
    const float* n_hid1 = (const float*)d_in[13];

    float* out  = (float*)d_out;
    float* hn   = out + (size_t)TT * BB * 2 * HH;
    float* cn   = hn + (size_t)4 * BB * HH;

    static bool attr_set = false;
    if (!attr_set) {
        cudaFuncSetAttribute(recur_kernel,
                             cudaFuncAttributeMaxDynamicSharedMemorySize, 131072);
        attr_set = true;
    }

    dim3 gxgrid(HH / 64, TT, 8);
    dim3 ntgrid(16, 2, 8);
    dim3 ntblk(32, 8);

    // layer 0
    noiseT_kernel<<<ntgrid, ntblk>>>(n_hid0);
    gx_gemm_kernel<512><<<gxgrid, 128>>>(x, n_in0, w_ih0, b_ih0, b_hh0);
    zero_bar_kernel<<<1, 1>>>();
    recur_kernel<<<RC_CTAS, 256, 131072>>>(w_hh0, mask, out, 0, hn, cn);

    // layer 1
    noiseT_kernel<<<ntgrid, ntblk>>>(n_hid1);
    gx_gemm_kernel<1024><<<gxgrid, 128>>>(nullptr, n_in1, w_ih1, b_ih1, b_hh1);
    zero_bar_kernel<<<1, 1>>>();
    recur_kernel<<<RC_CTAS, 256, 131072>>>(w_hh1, mask, out, 1, hn, cn);
}

// round 6
// speedup vs baseline: 1.0585x; 1.0585x over previous
#include <cuda_runtime.h>
#include <stdint.h>

#define TT 256
#define BB 64
#define HH 512
#define RC_CTAS 128

typedef unsigned long long ull;

// -------- scratch (__device__ globals) --------
static __device__ float g_gx[(size_t)8 * TT * BB * HH];      // [dg][t][b][h]
static __device__ float g_out0[(size_t)TT * BB * 2 * HH];    // [t][b][2H]
static __device__ float g_gates[8 * HH * BB];                // [dg][h][b]
static __device__ float g_A[8 * HH * BB];                    // [dg][k][b]  (= h*noise)
static __device__ float g_noiseT[8 * HH * BB];               // [dg][h][b]
static __device__ float g_h[2 * HH * BB];                    // [d][h][b]
static __device__ float g_c[2 * HH * BB];                    // [d][h][b]
static __device__ unsigned g_bar_count;
static __device__ unsigned g_bar_gen;

// -------------------- helpers --------------------
__device__ __forceinline__ void ffma2(ull& d, ull a, ull b) {
    asm("fma.rn.f32x2 %0, %1, %2, %0;" : "+l"(d) : "l"(a), "l"(b));
}
__device__ __forceinline__ float2 unpack2(ull v) {
    float2 r;
    asm("mov.b64 {%0, %1}, %2;" : "=f"(r.x), "=f"(r.y) : "l"(v));
    return r;
}
__device__ __forceinline__ void cp_async16(uint32_t s, const void* g) {
    asm volatile("cp.async.ca.shared.global [%0], [%1], 16;" :: "r"(s), "l"(g));
}
__device__ __forceinline__ float fsig(float x) {
    return __fdividef(1.f, 1.f + __expf(-x));
}
__device__ __forceinline__ float ftanh(float x) {
    return 2.f * fsig(2.f * x) - 1.f;
}

// -------------------- barrier reset (stream-ordered) --------------------
__global__ void zero_bar_kernel() {
    g_bar_count = 0;
    g_bar_gen = 0;
}

// -------------------- noise transpose: [dg][b][h] -> [dg][h][b] ---------
__global__ void noiseT_kernel(const float* __restrict__ nh) {
    __shared__ float tile[32][33];
    int dg = blockIdx.z;
    int h0 = blockIdx.x * 32, b0 = blockIdx.y * 32;
    int x = threadIdx.x, y = threadIdx.y;   // 32 x 8
    #pragma unroll
    for (int i = 0; i < 32; i += 8)
        tile[y + i][x] = nh[(size_t)dg * BB * HH + (size_t)(b0 + y + i) * HH + h0 + x];
    __syncthreads();
    #pragma unroll
    for (int i = 0; i < 32; i += 8)
        g_noiseT[(size_t)dg * HH * BB + (size_t)(h0 + y + i) * BB + b0 + x] = tile[x][y + i];
}

// -------------------- gx GEMM v2: pipelined double buffer --------------
// C[t*B+b][h] = sum_k X[t,b,k]*Noise[dg,b,k]*W[dg,k,h] + (b_ih+b_hh)
// 64x64x16 tiles, 128 threads, 8x4 per thread via f32x2. One bar per chunk.
template<int K>
__global__ __launch_bounds__(128)
void gx_gemm_kernel(const float* __restrict__ X,
                    const float* __restrict__ Noise,
                    const float* __restrict__ W,
                    const float* __restrict__ bih,
                    const float* __restrict__ bhh)
{
    const int dg = blockIdx.z;
    const int mt = blockIdx.y;
    const int nt = blockIdx.x;
    const int tid = threadIdx.x;

    __shared__ float As[2][16][68];
    __shared__ float Bs[2][16][136];

    const float* Xbase = (K == 1024) ? (const float*)g_out0 : X;
    const float* Xp = Xbase + (size_t)mt * BB * K;
    const float* Np = Noise + (size_t)dg * BB * K;
    const float* Wp = W + (size_t)dg * K * HH + nt * 64;

    ull accp[4][4];
    #pragma unroll
    for (int p = 0; p < 4; p++)
        #pragma unroll
        for (int j = 0; j < 4; j++) accp[p][j] = 0ULL;

    const int a_lm = tid >> 2;          // 0..31
    const int a_lk = (tid & 3) * 4;     // 0,4,8,12
    const int b_lk = tid >> 4;          // 0..7
    const int b_ln = (tid & 15) * 4;    // 0..60
    const int tm = (tid >> 4) * 8;
    const int tn = (tid & 15) * 4;

    float4 xv0, xv1, nv0, nv1, wv0, wv1;

    auto ldg_chunk = [&](int k0) {
        xv0 = *reinterpret_cast<const float4*>(Xp + (size_t)a_lm * K + k0 + a_lk);
        nv0 = *reinterpret_cast<const float4*>(Np + (size_t)a_lm * K + k0 + a_lk);
        xv1 = *reinterpret_cast<const float4*>(Xp + (size_t)(a_lm + 32) * K + k0 + a_lk);
        nv1 = *reinterpret_cast<const float4*>(Np + (size_t)(a_lm + 32) * K + k0 + a_lk);
        wv0 = *reinterpret_cast<const float4*>(Wp + (size_t)(k0 + b_lk) * HH + b_ln);
        wv1 = *reinterpret_cast<const float4*>(Wp + (size_t)(k0 + b_lk + 8) * HH + b_ln);
    };
    auto sts_chunk = [&](int buf) {
        As[buf][a_lk + 0][a_lm] = xv0.x * nv0.x;
        As[buf][a_lk + 1][a_lm] = xv0.y * nv0.y;
        As[buf][a_lk + 2][a_lm] = xv0.z * nv0.z;
        As[buf][a_lk + 3][a_lm] = xv0.w * nv0.w;
        As[buf][a_lk + 0][a_lm + 32] = xv1.x * nv1.x;
        As[buf][a_lk + 1][a_lm + 32] = xv1.y * nv1.y;
        As[buf][a_lk + 2][a_lm + 32] = xv1.z * nv1.z;
        As[buf][a_lk + 3][a_lm + 32] = xv1.w * nv1.w;
        *reinterpret_cast<float4*>(&Bs[buf][b_lk][b_ln * 2]) =
            make_float4(wv0.x, wv0.x, wv0.y, wv0.y);
        *reinterpret_cast<float4*>(&Bs[buf][b_lk][b_ln * 2 + 4]) =
            make_float4(wv0.z, wv0.z, wv0.w, wv0.w);
        *reinterpret_cast<float4*>(&Bs[buf][b_lk + 8][b_ln * 2]) =
            make_float4(wv1.x, wv1.x, wv1.y, wv1.y);
        *reinterpret_cast<float4*>(&Bs[buf][b_lk + 8][b_ln * 2 + 4]) =
            make_float4(wv1.z, wv1.z, wv1.w, wv1.w);
    };

    const int NC = K / 16;
    ldg_chunk(0);
    sts_chunk(0);
    __syncthreads();

    #pragma unroll 1
    for (int ch = 0; ch < NC; ++ch) {
        if (ch + 1 < NC) ldg_chunk((ch + 1) * 16);   // prefetch into regs

        const int cur = ch & 1;
        #pragma unroll
        for (int kk = 0; kk < 16; kk++) {
            ulonglong2 av0 = *reinterpret_cast<const ulonglong2*>(&As[cur][kk][tm]);
            ulonglong2 av1 = *reinterpret_cast<const ulonglong2*>(&As[cur][kk][tm + 4]);
            ulonglong2 bv0 = *reinterpret_cast<const ulonglong2*>(&Bs[cur][kk][tn * 2]);
            ulonglong2 bv1 = *reinterpret_cast<const ulonglong2*>(&Bs[cur][kk][tn * 2 + 4]);
            ull a[4] = {av0.x, av0.y, av1.x, av1.y};
            ull b[4] = {bv0.x, bv0.y, bv1.x, bv1.y};
            #pragma unroll
            for (int p = 0; p < 4; p++)
                #pragma unroll
                for (int j = 0; j < 4; j++)
                    ffma2(accp[p][j], a[p], b[j]);
        }

        if (ch + 1 < NC) {
            sts_chunk((ch + 1) & 1);
            __syncthreads();
        }
    }

    float bias[4];
    #pragma unroll
    for (int j = 0; j < 4; j++)
        bias[j] = bih[dg * HH + nt * 64 + tn + j] + bhh[dg * HH + nt * 64 + tn + j];

    float* Cp = g_gx + ((size_t)dg * TT + mt) * BB * HH;
    #pragma unroll
    for (int p = 0; p < 4; p++) {
        float2 u[4];
        #pragma unroll
        for (int j = 0; j < 4; j++) u[j] = unpack2(accp[p][j]);
        float4 v0 = make_float4(u[0].x + bias[0], u[1].x + bias[1],
                                u[2].x + bias[2], u[3].x + bias[3]);
        float4 v1 = make_float4(u[0].y + bias[0], u[1].y + bias[1],
                                u[2].y + bias[2], u[3].y + bias[3]);
        *reinterpret_cast<float4*>(Cp + (size_t)(tm + 2 * p) * HH + nt * 64 + tn) = v0;
        *reinterpret_cast<float4*>(Cp + (size_t)(tm + 2 * p + 1) * HH + nt * 64 + tn) = v1;
    }
}

// -------------------- persistent recurrence (R4 struct, v3 plumbing) ----
// CTA cta: dg = cta>>4, nt = cta&15 -> 32 cols of gate dg.
// Ws: w_hh slice duplicated [512][64] in dynamic smem (128KB).
// 3-buffer cp.async A staging; leader-release grid barrier (2/step).
__global__ __launch_bounds__(256, 1)
void recur_kernel(const float* __restrict__ Whh,
                  const float* __restrict__ mask,
                  float* __restrict__ outp,
                  int layer,
                  float* __restrict__ hn,
                  float* __restrict__ cn)
{
    extern __shared__ float Ws[];                    // [512][64] duplicated = 128KB
    __shared__ __align__(16) float Asb[3][16][64];   // 12KB, 3-stage ring

    const int cta = blockIdx.x;
    const int dg  = cta >> 4;
    const int d   = dg >> 2;
    const int nt  = cta & 15;
    const int tid = threadIdx.x;

    float* op = (layer == 0) ? (float*)g_out0 : outp;

    // ---- load W slice duplicated
    {
        const float* Wp = Whh + (size_t)dg * HH * HH + nt * 32;
        for (int i = tid; i < 512 * 8; i += 256) {
            int k = i >> 3;
            int c4 = (i & 7) * 4;
            float4 w = *reinterpret_cast<const float4*>(Wp + (size_t)k * HH + c4);
            *reinterpret_cast<float4*>(&Ws[k * 64 + c4 * 2])     = make_float4(w.x, w.x, w.y, w.y);
            *reinterpret_cast<float4*>(&Ws[k * 64 + c4 * 2 + 4]) = make_float4(w.z, w.z, w.w, w.w);
        }
    }
    // ---- zero state slices
    for (int i = tid; i < 512; i += 256) { g_h[cta * 512 + i] = 0.f; g_c[cta * 512 + i] = 0.f; }
    for (int i = tid; i < 2048; i += 256) g_A[cta * 2048 + i] = 0.f;

    // ---- leader-release grid barrier (monotonic; reset by zero_bar) ----
    unsigned bar_n = 0;
    auto grid_bar = [&]() {
        __syncthreads();
        ++bar_n;
        if (tid == 0) {
            asm volatile("red.release.gpu.global.add.u32 [%0], %1;"
                         :: "l"(&g_bar_count), "r"(1u) : "memory");
            if (cta == 0) {
                unsigned c;
                do {
                    asm volatile("ld.acquire.gpu.global.u32 %0, [%1];"
                                 : "=r"(c) : "l"(&g_bar_count) : "memory");
                } while (c < bar_n * RC_CTAS);
                asm volatile("st.release.gpu.global.u32 [%0], %1;"
                             :: "l"(&g_bar_gen), "r"(bar_n) : "memory");
            } else {
                unsigned gv;
                do {
                    asm volatile("ld.acquire.gpu.global.u32 %0, [%1];"
                                 : "=r"(gv) : "l"(&g_bar_gen) : "memory");
                } while (gv < bar_n);
            }
        }
        __syncthreads();
    };

    grid_bar();

    // warp tile mapping (as R4): 8 col-pairs x 4 batch-groups per warp
    const int tc = ((tid >> 5) & 1) * 8 + (tid & 7);           // 0..15 col-pair
    const int tm = (((tid >> 6) << 2) + ((tid >> 3) & 3)) * 4; // 0..60 batch base
    const float* Abase = g_A + (size_t)dg * HH * BB;
    const uint32_t as_u32 = (uint32_t)__cvta_generic_to_shared(&Asb[0][0][0]);
    const float* wsp = Ws + tc * 4;

    for (int step = 0; step < TT; ++step) {
        const int t = (d == 0) ? step : (TT - 1 - step);

        // prefetch gx for epilogue
        const float* gxp = g_gx + ((size_t)dg * TT + t) * BB * HH;
        const int c0 = nt * 32 + tc * 2;
        float2 gxb[4];
        #pragma unroll
        for (int p = 0; p < 4; p++)
            gxb[p] = *reinterpret_cast<const float2*>(gxp + (size_t)(tm + p) * HH + c0);

        // ---- GEMM: 3-stage cp.async pipeline over 32 chunks of A ----
        cp_async16(as_u32 + 0 * 4096 + tid * 16, Abase + 0 * 1024 + tid * 4);
        asm volatile("cp.async.commit_group;");
        cp_async16(as_u32 + 1 * 4096 + tid * 16, Abase + 1 * 1024 + tid * 4);
        asm volatile("cp.async.commit_group;");

        ull a00 = 0, a01 = 0, a10 = 0, a11 = 0;
        #pragma unroll 1
        for (int ch = 0; ch < 32; ++ch) {
            asm volatile("cp.async.wait_group 1;");
            __syncthreads();

            const float* asr = &Asb[0][0][0] + (ch % 3) * 1024;
            const float* wr  = wsp + (ch << 8);    // ch*16*16... (see stride below)
            #pragma unroll
            for (int kk = 0; kk < 16; kk++) {
                ulonglong2 a2 = *reinterpret_cast<const ulonglong2*>(asr + kk * 64 + tm);
                ulonglong2 w2 = *reinterpret_cast<const ulonglong2*>(
                    wsp + (size_t)(ch * 16 + kk) * 64);
                ffma2(a00, a2.x, w2.x);
                ffma2(a01, a2.y, w2.x);
                ffma2(a10, a2.x, w2.y);
                ffma2(a11, a2.y, w2.y);
            }
            (void)wr;

            if (ch + 2 < 32)
                cp_async16(as_u32 + ((ch + 2) % 3) * 4096 + tid * 16,
                           Abase + (size_t)(ch + 2) * 1024 + tid * 4);
            asm volatile("cp.async.commit_group;");   // empty group ok near tail
        }

        // ---- epilogue: gates[dg][c][b] = acc + gx ----
        {
            float2 u00 = unpack2(a00), u01 = unpack2(a01);
            float2 u10 = unpack2(a10), u11 = unpack2(a11);
            float4 v0 = make_float4(u00.x + gxb[0].x, u00.y + gxb[1].x,
                                    u01.x + gxb[2].x, u01.y + gxb[3].x);
            float4 v1 = make_float4(u10.x + gxb[0].y, u10.y + gxb[1].y,
                                    u11.x + gxb[2].y, u11.y + gxb[3].y);
            *reinterpret_cast<float4*>(g_gates + ((size_t)dg * HH + c0) * BB + tm) = v0;
            *reinterpret_cast<float4*>(g_gates + ((size_t)dg * HH + c0 + 1) * BB + tm) = v1;
        }

        grid_bar();

        // ---- pointwise: (d2, h, b-pair) map, coalesced ----
        {
            int idx = cta * 512 + tid * 2;
            int d2  = idx >> 15;
            int rem = idx & 32767;
            int h   = rem >> 6;
            int b   = rem & 63;
            int t2  = (d2 == 0) ? step : (TT - 1 - step);

            const float* gb = g_gates + ((size_t)d2 * 4 * HH + h) * BB + b;
            float2 gi = *reinterpret_cast<const float2*>(gb);
            float2 gf = *reinterpret_cast<const float2*>(gb + (size_t)HH * BB);
            float2 gg = *reinterpret_cast<const float2*>(gb + (size_t)2 * HH * BB);
            float2 go = *reinterpret_cast<const float2*>(gb + (size_t)3 * HH * BB);

            int sidx = (d2 * HH + h) * BB + b;
            float2 cp = *reinterpret_cast<float2*>(&g_c[sidx]);
            float2 hp = *reinterpret_cast<float2*>(&g_h[sidx]);
            float2 mt = *reinterpret_cast<const float2*>(mask + t2 * BB + b);

            float2 hm, cm;
            {
                float cnew = fsig(gf.x) * cp.x + fsig(gi.x) * ftanh(gg.x);
                float hnew = fsig(go.x) * ftanh(cnew);
                hm.x = hnew * mt.x + hp.x * (1.f - mt.x);
                cm.x = cnew * mt.x + cp.x * (1.f - mt.x);
            }
            {
                float cnew = fsig(gf.y) * cp.y + fsig(gi.y) * ftanh(gg.y);
                float hnew = fsig(go.y) * ftanh(cnew);
                hm.y = hnew * mt.y + hp.y * (1.f - mt.y);
                cm.y = cnew * mt.y + cp.y * (1.f - mt.y);
            }

            *reinterpret_cast<float2*>(&g_h[sidx]) = hm;
            *reinterpret_cast<float2*>(&g_c[sidx]) = cm;

            #pragma unroll
            for (int g = 0; g < 4; g++) {
                int ai = (((d2 * 4 + g) * HH) + h) * BB + b;
                float2 nz = *reinterpret_cast<const float2*>(&g_noiseT[ai]);
                *reinterpret_cast<float2*>(&g_A[ai]) = make_float2(hm.x * nz.x, hm.y * nz.y);
            }

            size_t ob = (size_t)t2 * BB * 2 * HH + (size_t)b * 2 * HH + d2 * HH + h;
            op[ob] = hm.x;
            op[ob + 2 * HH] = hm.y;

            if (step == TT - 1) {
                size_t oi = ((size_t)(layer * 2 + d2) * BB + b) * HH + h;
                hn[oi] = hm.x; hn[oi + HH] = hm.y;
                cn[oi] = cm.x; cn[oi + HH] = cm.y;
            }
        }

        grid_bar();
    }
}

// -------------------- launch --------------------
extern "C" void kernel_launch(void* const* d_in, const int* in_sizes, int n_in,
                              void* d_out, int out_size)
{
    const float* x      = (const float*)d_in[0];
    const float* mask   = (const float*)d_in[1];
    const float* w_ih0  = (const float*)d_in[2];
    const float* w_hh0  = (const float*)d_in[3];
    const float* b_ih0  = (const float*)d_in[4];
    const float* b_hh0  = (const float*)d_in[5];
    const float* n_in0  = (const float*)d_in[6];
    const float* n_hid0 = (const float*)d_in[7];
    const float* w_ih1  = (const float*)d_in[8];
    const float* w_hh1  = (const float*)d_in[9];
    const float* b_ih1  = (const float*)d_in[10];
    const float* b_hh1  = (const float*)d_in[11];
    const float* n_in1  = (const float*)d_in[12];
    const float* n_hid1 = (const float*)d_in[13];

    float* out  = (float*)d_out;
    float* hn   = out + (size_t)TT * BB * 2 * HH;
    float* cn   = hn + (size_t)4 * BB * HH;

    static bool attr_set = false;
    if (!attr_set) {
        cudaFuncSetAttribute(recur_kernel,
                             cudaFuncAttributeMaxDynamicSharedMemorySize, 131072);
        attr_set = true;
    }

    dim3 gxgrid(HH / 64, TT, 8);
    dim3 ntgrid(16, 2, 8);
    dim3 ntblk(32, 8);

    // layer 0
    noiseT_kernel<<<ntgrid, ntblk>>>(n_hid0);
    gx_gemm_kernel<512><<<gxgrid, 128>>>(x, n_in0, w_ih0, b_ih0, b_hh0);
    zero_bar_kernel<<<1, 1>>>();
    recur_kernel<<<RC_CTAS, 256, 131072>>>(w_hh0, mask, out, 0, hn, cn);

    // layer 1
    noiseT_kernel<<<ntgrid, ntblk>>>(n_hid1);
    gx_gemm_kernel<1024><<<gxgrid, 128>>>(nullptr, n_in1, w_ih1, b_ih1, b_hh1);
    zero_bar_kernel<<<1, 1>>>();
    recur_kernel<<<RC_CTAS, 256, 131072>>>(w_hh1, mask, out, 1, hn, cn);
}

// round 8
// speedup vs baseline: 1.2917x; 1.2204x over previous
#include <cuda_runtime.h>
#include <stdint.h>

#define TT 256
#define BB 64
#define HH 512
#define RC_CTAS 128

typedef unsigned long long ull;

// -------- scratch (__device__ globals) --------
static __device__ float g_gx[(size_t)8 * TT * BB * HH];      // [dg][t][b][h]
static __device__ float g_out0[(size_t)TT * BB * 2 * HH];    // [t][b][2H]
static __device__ float g_gates[8 * HH * BB];                // [dg][h][b]
static __device__ float g_A[8 * HH * BB];                    // [dg][k][b]  (= h*noise)
static __device__ float g_noiseT[8 * HH * BB];               // [dg][h][b]
static __device__ float g_h[2 * HH * BB];                    // [d][h][b]
static __device__ float g_c[2 * HH * BB];                    // [d][h][b]
static __device__ unsigned g_bar_count;
static __device__ unsigned g_bar_gen;

// -------------------- helpers --------------------
__device__ __forceinline__ void ffma2(ull& d, ull a, ull b) {
    asm("fma.rn.f32x2 %0, %1, %2, %0;" : "+l"(d) : "l"(a), "l"(b));
}
__device__ __forceinline__ float2 unpack2(ull v) {
    float2 r;
    asm("mov.b64 {%0, %1}, %2;" : "=f"(r.x), "=f"(r.y) : "l"(v));
    return r;
}
__device__ __forceinline__ void cp_async16(uint32_t s, const void* g) {
    asm volatile("cp.async.ca.shared.global [%0], [%1], 16;" :: "r"(s), "l"(g));
}
__device__ __forceinline__ float fsig(float x) {
    return __fdividef(1.f, 1.f + __expf(-x));
}
__device__ __forceinline__ float ftanh(float x) {
    return 2.f * fsig(2.f * x) - 1.f;
}
__device__ __forceinline__ void mma_tf32(float* d, const uint32_t* a, const uint32_t* b) {
    asm volatile(
        "mma.sync.aligned.m16n8k8.row.col.f32.tf32.tf32.f32 "
        "{%0,%1,%2,%3}, {%4,%5,%6,%7}, {%8,%9}, {%0,%1,%2,%3};"
        : "+f"(d[0]), "+f"(d[1]), "+f"(d[2]), "+f"(d[3])
        : "r"(a[0]), "r"(a[1]), "r"(a[2]), "r"(a[3]), "r"(b[0]), "r"(b[1]));
}
// Dekker split: hi = tf32-rounded a (fp32 container), lo = a - hi (exact)
__device__ __forceinline__ float2 tf32_split(float a) {
    uint32_t hb;
    asm("cvt.rna.tf32.f32 %0, %1;" : "=r"(hb) : "f"(a));
    float hi = __uint_as_float(hb);
    return make_float2(hi, a - hi);
}

// -------------------- barrier reset (stream-ordered) --------------------
__global__ void zero_bar_kernel() {
    g_bar_count = 0;
    g_bar_gen = 0;
}

// -------------------- noise transpose: [dg][b][h] -> [dg][h][b] ---------
__global__ void noiseT_kernel(const float* __restrict__ nh) {
    __shared__ float tile[32][33];
    int dg = blockIdx.z;
    int h0 = blockIdx.x * 32, b0 = blockIdx.y * 32;
    int x = threadIdx.x, y = threadIdx.y;   // 32 x 8
    #pragma unroll
    for (int i = 0; i < 32; i += 8)
        tile[y + i][x] = nh[(size_t)dg * BB * HH + (size_t)(b0 + y + i) * HH + h0 + x];
    __syncthreads();
    #pragma unroll
    for (int i = 0; i < 32; i += 8)
        g_noiseT[(size_t)dg * HH * BB + (size_t)(h0 + y + i) * BB + b0 + x] = tile[x][y + i];
}

// -------------------- gx GEMM v4: 3xTF32 tensor-core --------------------
// C[t*B+b][h] = sum_k X[t,b,k]*Noise[dg,b,k]*W[dg,k,h] + (b_ih+b_hh)
// 64x64x16 tiles, 128 threads (2x2 warps, m32xn32/warp), error-compensated tf32.
template<int K>
__global__ __launch_bounds__(128)
void gx_gemm_kernel(const float* __restrict__ X,
                    const float* __restrict__ Noise,
                    const float* __restrict__ W,
                    const float* __restrict__ bih,
                    const float* __restrict__ bhh)
{
    const int dg = blockIdx.z;
    const int mt = blockIdx.y;
    const int nt = blockIdx.x;
    const int tid = threadIdx.x;

    __shared__ __align__(16) float2 As[2][64][22];   // (hi,lo), pad 22: conflict-free
    __shared__ __align__(16) float2 Bs[2][16][72];   // (hi,lo), pad 72: <=2-way (free @64b)

    const float* Xbase = (K == 1024) ? (const float*)g_out0 : X;
    const float* Xp = Xbase + (size_t)mt * BB * K;
    const float* Np = Noise + (size_t)dg * BB * K;
    const float* Wp = W + (size_t)dg * K * HH + nt * 64;

    // staging indices
    const int a_lm = tid >> 2;          // 0..31  (m rows, +32 second half)
    const int a_lk = (tid & 3) * 4;     // 0,4,8,12
    const int b_lk = tid >> 4;          // 0..7   (k rows, +8 second half)
    const int b_ln = (tid & 15) * 4;    // 0..60

    // warp decomposition
    const int wid = tid >> 5;
    const int wm = wid >> 1;
    const int wn = wid & 1;
    const int lane = tid & 31;
    const int r = lane >> 2;            // 0..7
    const int c = lane & 3;             // 0..3

    float acc[2][4][4];
    #pragma unroll
    for (int i = 0; i < 2; i++)
        #pragma unroll
        for (int j = 0; j < 4; j++)
            #pragma unroll
            for (int q = 0; q < 4; q++) acc[i][j][q] = 0.f;

    float4 xv0, xv1, nv0, nv1, wv0, wv1;
    auto ldg_chunk = [&](int k0) {
        xv0 = *reinterpret_cast<const float4*>(Xp + (size_t)a_lm * K + k0 + a_lk);
        nv0 = *reinterpret_cast<const float4*>(Np + (size_t)a_lm * K + k0 + a_lk);
        xv1 = *reinterpret_cast<const float4*>(Xp + (size_t)(a_lm + 32) * K + k0 + a_lk);
        nv1 = *reinterpret_cast<const float4*>(Np + (size_t)(a_lm + 32) * K + k0 + a_lk);
        wv0 = *reinterpret_cast<const float4*>(Wp + (size_t)(k0 + b_lk) * HH + b_ln);
        wv1 = *reinterpret_cast<const float4*>(Wp + (size_t)(k0 + b_lk + 8) * HH + b_ln);
    };
    auto sts_chunk = [&](int buf) {
        As[buf][a_lm][a_lk + 0] = tf32_split(xv0.x * nv0.x);
        As[buf][a_lm][a_lk + 1] = tf32_split(xv0.y * nv0.y);
        As[buf][a_lm][a_lk + 2] = tf32_split(xv0.z * nv0.z);
        As[buf][a_lm][a_lk + 3] = tf32_split(xv0.w * nv0.w);
        As[buf][a_lm + 32][a_lk + 0] = tf32_split(xv1.x * nv1.x);
        As[buf][a_lm + 32][a_lk + 1] = tf32_split(xv1.y * nv1.y);
        As[buf][a_lm + 32][a_lk + 2] = tf32_split(xv1.z * nv1.z);
        As[buf][a_lm + 32][a_lk + 3] = tf32_split(xv1.w * nv1.w);
        Bs[buf][b_lk][b_ln + 0] = tf32_split(wv0.x);
        Bs[buf][b_lk][b_ln + 1] = tf32_split(wv0.y);
        Bs[buf][b_lk][b_ln + 2] = tf32_split(wv0.z);
        Bs[buf][b_lk][b_ln + 3] = tf32_split(wv0.w);
        Bs[buf][b_lk + 8][b_ln + 0] = tf32_split(wv1.x);
        Bs[buf][b_lk + 8][b_ln + 1] = tf32_split(wv1.y);
        Bs[buf][b_lk + 8][b_ln + 2] = tf32_split(wv1.z);
        Bs[buf][b_lk + 8][b_ln + 3] = tf32_split(wv1.w);
    };

    const int NC = K / 16;
    ldg_chunk(0);
    sts_chunk(0);
    __syncthreads();

    #pragma unroll 1
    for (int ch = 0; ch < NC; ++ch) {
        if (ch + 1 < NC) ldg_chunk((ch + 1) * 16);

        const int cur = ch & 1;
        #pragma unroll
        for (int ks = 0; ks < 2; ks++) {
            const int kb = ks * 8;
            // A fragments: hi and lo
            uint32_t ah[2][4], al[2][4];
            #pragma unroll
            for (int mt2 = 0; mt2 < 2; mt2++) {
                const int mb = wm * 32 + mt2 * 16;
                float2 f0 = As[cur][mb + r][kb + c];
                float2 f1 = As[cur][mb + r + 8][kb + c];
                float2 f2 = As[cur][mb + r][kb + c + 4];
                float2 f3 = As[cur][mb + r + 8][kb + c + 4];
                ah[mt2][0] = __float_as_uint(f0.x); al[mt2][0] = __float_as_uint(f0.y);
                ah[mt2][1] = __float_as_uint(f1.x); al[mt2][1] = __float_as_uint(f1.y);
                ah[mt2][2] = __float_as_uint(f2.x); al[mt2][2] = __float_as_uint(f2.y);
                ah[mt2][3] = __float_as_uint(f3.x); al[mt2][3] = __float_as_uint(f3.y);
            }
            // B fragments: hi and lo
            uint32_t bh[4][2], bl[4][2];
            #pragma unroll
            for (int n2 = 0; n2 < 4; n2++) {
                const int nb = wn * 32 + n2 * 8 + r;
                float2 f0 = Bs[cur][kb + c][nb];
                float2 f1 = Bs[cur][kb + c + 4][nb];
                bh[n2][0] = __float_as_uint(f0.x); bl[n2][0] = __float_as_uint(f0.y);
                bh[n2][1] = __float_as_uint(f1.x); bl[n2][1] = __float_as_uint(f1.y);
            }
            #pragma unroll
            for (int mt2 = 0; mt2 < 2; mt2++)
                #pragma unroll
                for (int n2 = 0; n2 < 4; n2++) {
                    mma_tf32(acc[mt2][n2], ah[mt2], bl[n2]);   // hi*lo
                    mma_tf32(acc[mt2][n2], al[mt2], bh[n2]);   // lo*hi
                    mma_tf32(acc[mt2][n2], ah[mt2], bh[n2]);   // hi*hi
                }
        }

        if (ch + 1 < NC) {
            sts_chunk((ch + 1) & 1);
            __syncthreads();
        }
    }

    // epilogue: D[b][h] + bias -> g_gx[dg][t][b][h]
    float* Cp = g_gx + ((size_t)dg * TT + mt) * BB * HH;
    #pragma unroll
    for (int mt2 = 0; mt2 < 2; mt2++) {
        #pragma unroll
        for (int n2 = 0; n2 < 4; n2++) {
            const int b0 = wm * 32 + mt2 * 16 + r;
            const int h0 = nt * 64 + wn * 32 + n2 * 8 + 2 * c;
            float bx = bih[dg * HH + h0]     + bhh[dg * HH + h0];
            float by = bih[dg * HH + h0 + 1] + bhh[dg * HH + h0 + 1];
            *reinterpret_cast<float2*>(Cp + (size_t)b0 * HH + h0) =
                make_float2(acc[mt2][n2][0] + bx, acc[mt2][n2][1] + by);
            *reinterpret_cast<float2*>(Cp + (size_t)(b0 + 8) * HH + h0) =
                make_float2(acc[mt2][n2][2] + bx, acc[mt2][n2][3] + by);
        }
    }
}

// -------------------- persistent recurrence (unchanged from R6) ----
__global__ __launch_bounds__(256, 1)
void recur_kernel(const float* __restrict__ Whh,
                  const float* __restrict__ mask,
                  float* __restrict__ outp,
                  int layer,
                  float* __restrict__ hn,
                  float* __restrict__ cn)
{
    extern __shared__ float Ws[];                    // [512][64] duplicated = 128KB
    __shared__ __align__(16) float Asb[3][16][64];   // 12KB, 3-stage ring

    const int cta = blockIdx.x;
    const int dg  = cta >> 4;
    const int d   = dg >> 2;
    const int nt  = cta & 15;
    const int tid = threadIdx.x;

    float* op = (layer == 0) ? (float*)g_out0 : outp;

    {
        const float* Wp = Whh + (size_t)dg * HH * HH + nt * 32;
        for (int i = tid; i < 512 * 8; i += 256) {
            int k = i >> 3;
            int c4 = (i & 7) * 4;
            float4 w = *reinterpret_cast<const float4*>(Wp + (size_t)k * HH + c4);
            *reinterpret_cast<float4*>(&Ws[k * 64 + c4 * 2])     = make_float4(w.x, w.x, w.y, w.y);
            *reinterpret_cast<float4*>(&Ws[k * 64 + c4 * 2 + 4]) = make_float4(w.z, w.z, w.w, w.w);
        }
    }
    for (int i = tid; i < 512; i += 256) { g_h[cta * 512 + i] = 0.f; g_c[cta * 512 + i] = 0.f; }
    for (int i = tid; i < 2048; i += 256) g_A[cta * 2048 + i] = 0.f;

    unsigned bar_n = 0;
    auto grid_bar = [&]() {
        __syncthreads();
        ++bar_n;
        if (tid == 0) {
            asm volatile("red.release.gpu.global.add.u32 [%0], %1;"
                         :: "l"(&g_bar_count), "r"(1u) : "memory");
            if (cta == 0) {
                unsigned c;
                do {
                    asm volatile("ld.acquire.gpu.global.u32 %0, [%1];"
                                 : "=r"(c) : "l"(&g_bar_count) : "memory");
                } while (c < bar_n * RC_CTAS);
                asm volatile("st.release.gpu.global.u32 [%0], %1;"
                             :: "l"(&g_bar_gen), "r"(bar_n) : "memory");
            } else {
                unsigned gv;
                do {
                    asm volatile("ld.acquire.gpu.global.u32 %0, [%1];"
                                 : "=r"(gv) : "l"(&g_bar_gen) : "memory");
                } while (gv < bar_n);
            }
        }
        __syncthreads();
    };

    grid_bar();

    const int tc = ((tid >> 5) & 1) * 8 + (tid & 7);           // 0..15 col-pair
    const int tm = (((tid >> 6) << 2) + ((tid >> 3) & 3)) * 4; // 0..60 batch base
    const float* Abase = g_A + (size_t)dg * HH * BB;
    const uint32_t as_u32 = (uint32_t)__cvta_generic_to_shared(&Asb[0][0][0]);
    const float* wsp = Ws + tc * 4;

    for (int step = 0; step < TT; ++step) {
        const int t = (d == 0) ? step : (TT - 1 - step);

        const float* gxp = g_gx + ((size_t)dg * TT + t) * BB * HH;
        const int c0 = nt * 32 + tc * 2;
        float2 gxb[4];
        #pragma unroll
        for (int p = 0; p < 4; p++)
            gxb[p] = *reinterpret_cast<const float2*>(gxp + (size_t)(tm + p) * HH + c0);

        cp_async16(as_u32 + 0 * 4096 + tid * 16, Abase + 0 * 1024 + tid * 4);
        asm volatile("cp.async.commit_group;");
        cp_async16(as_u32 + 1 * 4096 + tid * 16, Abase + 1 * 1024 + tid * 4);
        asm volatile("cp.async.commit_group;");

        ull a00 = 0, a01 = 0, a10 = 0, a11 = 0;
        #pragma unroll 1
        for (int ch = 0; ch < 32; ++ch) {
            asm volatile("cp.async.wait_group 1;");
            __syncthreads();

            const float* asr = &Asb[0][0][0] + (ch % 3) * 1024;
            #pragma unroll
            for (int kk = 0; kk < 16; kk++) {
                ulonglong2 a2 = *reinterpret_cast<const ulonglong2*>(asr + kk * 64 + tm);
                ulonglong2 w2 = *reinterpret_cast<const ulonglong2*>(
                    wsp + (size_t)(ch * 16 + kk) * 64);
                ffma2(a00, a2.x, w2.x);
                ffma2(a01, a2.y, w2.x);
                ffma2(a10, a2.x, w2.y);
                ffma2(a11, a2.y, w2.y);
            }

            if (ch + 2 < 32)
                cp_async16(as_u32 + ((ch + 2) % 3) * 4096 + tid * 16,
                           Abase + (size_t)(ch + 2) * 1024 + tid * 4);
            asm volatile("cp.async.commit_group;");
        }

        {
            float2 u00 = unpack2(a00), u01 = unpack2(a01);
            float2 u10 = unpack2(a10), u11 = unpack2(a11);
            float4 v0 = make_float4(u00.x + gxb[0].x, u00.y + gxb[1].x,
                                    u01.x + gxb[2].x, u01.y + gxb[3].x);
            float4 v1 = make_float4(u10.x + gxb[0].y, u10.y + gxb[1].y,
                                    u11.x + gxb[2].y, u11.y + gxb[3].y);
            *reinterpret_cast<float4*>(g_gates + ((size_t)dg * HH + c0) * BB + tm) = v0;
            *reinterpret_cast<float4*>(g_gates + ((size_t)dg * HH + c0 + 1) * BB + tm) = v1;
        }

        grid_bar();

        {
            int idx = cta * 512 + tid * 2;
            int d2  = idx >> 15;
            int rem = idx & 32767;
            int h   = rem >> 6;
            int b   = rem & 63;
            int t2  = (d2 == 0) ? step : (TT - 1 - step);

            const float* gb = g_gates + ((size_t)d2 * 4 * HH + h) * BB + b;
            float2 gi = *reinterpret_cast<const float2*>(gb);
            float2 gf = *reinterpret_cast<const float2*>(gb + (size_t)HH * BB);
            float2 gg = *reinterpret_cast<const float2*>(gb + (size_t)2 * HH * BB);
            float2 go = *reinterpret_cast<const float2*>(gb + (size_t)3 * HH * BB);

            int sidx = (d2 * HH + h) * BB + b;
            float2 cp = *reinterpret_cast<float2*>(&g_c[sidx]);
            float2 hp = *reinterpret_cast<float2*>(&g_h[sidx]);
            float2 mt = *reinterpret_cast<const float2*>(mask + t2 * BB + b);

            float2 hm, cm;
            {
                float cnew = fsig(gf.x) * cp.x + fsig(gi.x) * ftanh(gg.x);
                float hnew = fsig(go.x) * ftanh(cnew);
                hm.x = hnew * mt.x + hp.x * (1.f - mt.x);
                cm.x = cnew * mt.x + cp.x * (1.f - mt.x);
            }
            {
                float cnew = fsig(gf.y) * cp.y + fsig(gi.y) * ftanh(gg.y);
                float hnew = fsig(go.y) * ftanh(cnew);
                hm.y = hnew * mt.y + hp.y * (1.f - mt.y);
                cm.y = cnew * mt.y + cp.y * (1.f - mt.y);
            }

            *reinterpret_cast<float2*>(&g_h[sidx]) = hm;
            *reinterpret_cast<float2*>(&g_c[sidx]) = cm;

            #pragma unroll
            for (int g = 0; g < 4; g++) {
                int ai = (((d2 * 4 + g) * HH) + h) * BB + b;
                float2 nz = *reinterpret_cast<const float2*>(&g_noiseT[ai]);
                *reinterpret_cast<float2*>(&g_A[ai]) = make_float2(hm.x * nz.x, hm.y * nz.y);
            }

            size_t ob = (size_t)t2 * BB * 2 * HH + (size_t)b * 2 * HH + d2 * HH + h;
            op[ob] = hm.x;
            op[ob + 2 * HH] = hm.y;

            if (step == TT - 1) {
                size_t oi = ((size_t)(layer * 2 + d2) * BB + b) * HH + h;
                hn[oi] = hm.x; hn[oi + HH] = hm.y;
                cn[oi] = cm.x; cn[oi + HH] = cm.y;
            }
        }

        grid_bar();
    }
}

// -------------------- launch --------------------
extern "C" void kernel_launch(void* const* d_in, const int* in_sizes, int n_in,
                              void* d_out, int out_size)
{
    const float* x      = (const float*)d_in[0];
    const float* mask   = (const float*)d_in[1];
    const float* w_ih0  = (const float*)d_in[2];
    const float* w_hh0  = (const float*)d_in[3];
    const float* b_ih0  = (const float*)d_in[4];
    const float* b_hh0  = (const float*)d_in[5];
    const float* n_in0  = (const float*)d_in[6];
    const float* n_hid0 = (const float*)d_in[7];
    const float* w_ih1  = (const float*)d_in[8];
    const float* w_hh1  = (const float*)d_in[9];
    const float* b_ih1  = (const float*)d_in[10];
    const float* b_hh1  = (const float*)d_in[11];
    const float* n_in1  = (const float*)d_in[12];
    const float* n_hid1 = (const float*)d_in[13];

    float* out  = (float*)d_out;
    float* hn   = out + (size_t)TT * BB * 2 * HH;
    float* cn   = hn + (size_t)4 * BB * HH;

    static bool attr_set = false;
    if (!attr_set) {
        cudaFuncSetAttribute(recur_kernel,
                             cudaFuncAttributeMaxDynamicSharedMemorySize, 131072);
        attr_set = true;
    }

    dim3 gxgrid(HH / 64, TT, 8);
    dim3 ntgrid(16, 2, 8);
    dim3 ntblk(32, 8);

    // layer 0
    noiseT_kernel<<<ntgrid, ntblk>>>(n_hid0);
    gx_gemm_kernel<512><<<gxgrid, 128>>>(x, n_in0, w_ih0, b_ih0, b_hh0);
    zero_bar_kernel<<<1, 1>>>();
    recur_kernel<<<RC_CTAS, 256, 131072>>>(w_hh0, mask, out, 0, hn, cn);

    // layer 1
    noiseT_kernel<<<ntgrid, ntblk>>>(n_hid1);
    gx_gemm_kernel<1024><<<gxgrid, 128>>>(nullptr, n_in1, w_ih1, b_ih1, b_hh1);
    zero_bar_kernel<<<1, 1>>>();
    recur_kernel<<<RC_CTAS, 256, 131072>>>(w_hh1, mask, out, 1, hn, cn);
}